// round 15
// baseline (speedup 1.0000x reference)
#include <cuda_runtime.h>
#include <cstdint>

// DETR-style postprocess, two-phase balanced design:
//   K1: 296 blocks x 1024 thr, element-partitioned stream (perfect SM balance),
//       smem candidate buffer, single coalesced flush per block. No global atomics.
//   K2: 256 blocks x 512 thr, per-batch gather from <=3 chunk buffers + exact rank.
// Output concatenated flat f32: labels | boxes | scores. (verified R3)

#define BATCH    256
#define QQ       1000
#define CC       80
#define NELEM    80000
#define NV4      20000
#define NV4TOT   (BATCH * NV4)         // 5,120,000 float4
#define KTOP     300
#define CAP      4096
#define NBINS    2048
#define T_STATIC 2.5f

#define GRID1    296
#define NT1      1024
#define QCH      (NV4TOT / GRID1)      // 17297
#define RCH      (NV4TOT % GRID1)      // 88
#define SPLIT    (RCH * (QCH + 1))     // 1,522,224
#define LOCCAP   1024                  // per-chunk candidate cap (mean ~433, sd ~21)

#define NT2      512

#define LBL_OFF  0
#define BOX_OFF  (BATCH * KTOP)            // 76800
#define SCR_OFF  (BATCH * KTOP * 5)        // 384000

// Per-chunk candidate buffers. g_num is overwritten fresh by every K1 launch,
// so no reset logic is needed for graph replay.
__device__ unsigned long long g_buf[GRID1][LOCCAP];
__device__ int g_num[GRID1];

__device__ __forceinline__ unsigned f2key(float x) {
    unsigned b = __float_as_uint(x);
    return (b & 0x80000000u) ? ~b : (b | 0x80000000u);
}
__device__ __forceinline__ float key2f(unsigned k) {
    unsigned b = (k & 0x80000000u) ? (k & 0x7FFFFFFFu) : ~k;
    return __uint_as_float(b);
}
__device__ __forceinline__ int chunk_start(int c) {
    return c * QCH + min(c, RCH);
}
__device__ __forceinline__ int blk_of(int x) {   // chunk owning f4 index x
    return (x < SPLIT) ? (x / (QCH + 1)) : (RCH + (x - SPLIT) / QCH);
}

// ------------------------------------------------------------------
// Kernel 1: balanced element-partitioned filter
// ------------------------------------------------------------------
__global__ __launch_bounds__(NT1, 2)
void filter_kernel(const float* __restrict__ logits)
{
    __shared__ __align__(16) unsigned long long s_pack[LOCCAP];
    __shared__ int s_cnt;

    const int blk = blockIdx.x;
    const int tid = threadIdx.x;
    const float4* lg4 = (const float4*)logits;

    const int start = chunk_start(blk);
    const int n     = QCH + (blk < RCH ? 1 : 0);

    if (tid == 0) s_cnt = 0;
    __syncthreads();

    // proven R8 streaming body: MLP=4 front-batched, per-element test,
    // smem-atomic push. Pack carries the GLOBAL f4-element index.
    #pragma unroll 1
    for (int it = 0; it < 4; it++) {                  // 4 * 4096 = 16384 f4
        int base = start + it * (4 * NT1) + tid;
        float4 v0 = lg4[base];
        float4 v1 = lg4[base + NT1];
        float4 v2 = lg4[base + 2 * NT1];
        float4 v3 = lg4[base + 3 * NT1];
        float vv[16] = {v0.x, v0.y, v0.z, v0.w,  v1.x, v1.y, v1.z, v1.w,
                        v2.x, v2.y, v2.z, v2.w,  v3.x, v3.y, v3.z, v3.w};
        #pragma unroll
        for (int k = 0; k < 16; k++) {
            if (vv[k] > T_STATIC) {
                int pos = atomicAdd(&s_cnt, 1);
                if (pos < LOCCAP) {
                    unsigned gi = (unsigned)(base + (k >> 2) * NT1) * 4u + (unsigned)(k & 3);
                    s_pack[pos] = ((unsigned long long)f2key(vv[k]) << 32)
                                  | (unsigned long long)(~gi);
                }
            }
        }
    }
    {   // tail: rem in {913, 914} < NT1 -> one guarded load
        int rem = n - 16384;
        if (tid < rem) {
            int x = start + 16384 + tid;
            float4 v = lg4[x];
            float vv[4] = {v.x, v.y, v.z, v.w};
            #pragma unroll
            for (int j = 0; j < 4; j++) {
                if (vv[j] > T_STATIC) {
                    int pos = atomicAdd(&s_cnt, 1);
                    if (pos < LOCCAP) {
                        unsigned gi = (unsigned)x * 4u + (unsigned)j;
                        s_pack[pos] = ((unsigned long long)f2key(vv[j]) << 32)
                                      | (unsigned long long)(~gi);
                    }
                }
            }
        }
    }
    __syncthreads();

    // single coalesced flush; raw count published (overflow detectable by K2)
    const int cnt  = s_cnt;
    const int my_n = min(cnt, LOCCAP);
    if (tid == 0) g_num[blk] = cnt;
    for (int i = tid; i < my_n; i += NT1)
        g_buf[blk][i] = s_pack[i];
}

// ------------------------------------------------------------------
// Kernel 2: per-batch gather + exact rank (+exact radix fallback)
// ------------------------------------------------------------------
__global__ __launch_bounds__(NT2)
void rank_kernel(const float* __restrict__ logits,
                 const float* __restrict__ boxes,
                 float* __restrict__ out)
{
    __shared__ __align__(16) unsigned long long s_pack[CAP];
    __shared__ unsigned s_hist[NBINS];
    __shared__ int s_cnt, s_ovf;
    __shared__ int s_b1, s_gt, s_b2;

    const int b   = blockIdx.x;
    const int tid = threadIdx.x;
    const float4* lg4 = (const float4*)(logits + (size_t)b * NELEM);

    const unsigned lo = (unsigned)b * (unsigned)NELEM;        // element range
    const unsigned hi = lo + (unsigned)NELEM;
    const int c0 = blk_of(b * NV4);
    const int c1 = blk_of(b * NV4 + NV4 - 1);                  // c1 - c0 <= 2

    if (tid == 0) { s_cnt = 0; s_ovf = 0; }
    __syncthreads();

    // gather candidates belonging to this batch; re-base idx to local
    for (int c = c0; c <= c1; c++) {
        int nc = g_num[c];
        if (nc > LOCCAP) { if (tid == 0) s_ovf = 1; nc = LOCCAP; }
        for (int i = tid; i < nc; i += NT2) {
            unsigned long long p = g_buf[c][i];
            unsigned gi = ~(unsigned)(p & 0xFFFFFFFFull);
            if (gi >= lo && gi < hi) {
                int pos = atomicAdd(&s_cnt, 1);
                if (pos < CAP)
                    s_pack[pos] = (p & 0xFFFFFFFF00000000ull)
                                  | (unsigned long long)(~(gi - lo));
            }
        }
    }
    __syncthreads();
    int M = s_cnt;

    // ---------- Fallback: exact 2-level radix select (statistically never) ----------
    if (M < KTOP || M > CAP || s_ovf) {
        for (int i = tid; i < NBINS; i += NT2) s_hist[i] = 0;
        __syncthreads();
        for (int i = tid; i < NV4; i += NT2) {
            float4 v = lg4[i];
            float vv[4] = {v.x, v.y, v.z, v.w};
            #pragma unroll
            for (int j = 0; j < 4; j++)
                atomicAdd(&s_hist[f2key(vv[j]) >> 21], 1u);
        }
        __syncthreads();
        if (tid == 0) {
            int acc = 0, b1 = 0;
            for (int bin = NBINS - 1; bin >= 0; bin--) {
                int c = (int)s_hist[bin];
                if (acc + c >= KTOP) { b1 = bin; break; }
                acc += c;
            }
            s_b1 = b1; s_gt = acc;
        }
        __syncthreads();
        const int b1 = s_b1;
        const int cnt_ge = s_gt + (int)s_hist[b1];

        if (cnt_ge <= CAP) {
            if (tid == 0) s_cnt = 0;
            __syncthreads();
            for (int i = tid; i < NV4; i += NT2) {
                float4 v = lg4[i];
                float vv[4] = {v.x, v.y, v.z, v.w};
                #pragma unroll
                for (int j = 0; j < 4; j++) {
                    unsigned key = f2key(vv[j]);
                    if ((int)(key >> 21) >= b1) {
                        int pos = atomicAdd(&s_cnt, 1);
                        unsigned idx = (unsigned)(i * 4 + j);
                        s_pack[pos] = ((unsigned long long)key << 32)
                                      | (unsigned long long)(~idx);
                    }
                }
            }
            __syncthreads();
            M = s_cnt;
        } else {
            for (int i = tid; i < NBINS; i += NT2) s_hist[i] = 0;
            __syncthreads();
            for (int i = tid; i < NV4; i += NT2) {
                float4 v = lg4[i];
                float vv[4] = {v.x, v.y, v.z, v.w};
                #pragma unroll
                for (int j = 0; j < 4; j++) {
                    unsigned key = f2key(vv[j]);
                    if ((int)(key >> 21) == b1)
                        atomicAdd(&s_hist[(key >> 10) & 0x7FFu], 1u);
                }
            }
            __syncthreads();
            if (tid == 0) {
                int need = KTOP - s_gt;
                int acc = 0, b2 = 0;
                for (int bin = NBINS - 1; bin >= 0; bin--) {
                    int c = (int)s_hist[bin];
                    if (acc + c >= need) { b2 = bin; break; }
                    acc += c;
                }
                s_b2 = b2; s_cnt = 0;
            }
            __syncthreads();
            const int b2 = s_b2;
            for (int i = tid; i < NV4; i += NT2) {
                float4 v = lg4[i];
                float vv[4] = {v.x, v.y, v.z, v.w};
                #pragma unroll
                for (int j = 0; j < 4; j++) {
                    unsigned key = f2key(vv[j]);
                    int hb = (int)(key >> 21);
                    bool take = (hb > b1) ||
                                (hb == b1 && (int)((key >> 10) & 0x7FFu) >= b2);
                    if (take) {
                        int pos = atomicAdd(&s_cnt, 1);
                        if (pos < CAP) {
                            unsigned idx = (unsigned)(i * 4 + j);
                            s_pack[pos] = ((unsigned long long)key << 32)
                                          | (unsigned long long)(~idx);
                        }
                    }
                }
            }
            __syncthreads();
            M = min(s_cnt, CAP);
        }
    }

    // zero pad (sorts below every real pack -> never affects ranks)
    if (tid == 0 && M < CAP) s_pack[M] = 0ULL;
    __syncthreads();
    const int Mpair = (M + 1) >> 1;
    const ulonglong2* sp2 = (const ulonglong2*)s_pack;

    // exact ranking: descending key, lower idx first on ties
    for (int i = tid; i < M; i += NT2) {
        unsigned long long pi = s_pack[i];
        int r = 0;
        for (int j = 0; j < Mpair; j++) {
            ulonglong2 pj = sp2[j];
            r += (pj.x > pi) + (pj.y > pi);
        }
        if (r < KTOP) {
            unsigned key = (unsigned)(pi >> 32);
            unsigned idx = ~(unsigned)(pi & 0xFFFFFFFFull);
            int q = (int)(idx / CC);
            int c = (int)(idx % CC);
            float lv = key2f(key);
            float score = 1.0f / (1.0f + expf(-lv));

            size_t slot = (size_t)b * KTOP + r;
            out[LBL_OFF + slot] = (float)c;
            out[SCR_OFF + slot] = score;

            float4 bx = ((const float4*)boxes)[(size_t)b * QQ + q];
            float4 o;
            o.x = bx.x - 0.5f * bx.z;
            o.y = bx.y - 0.5f * bx.w;
            o.z = bx.x + 0.5f * bx.z;
            o.w = bx.y + 0.5f * bx.w;
            ((float4*)(out + BOX_OFF))[slot] = o;
        }
    }
}

extern "C" void kernel_launch(void* const* d_in, const int* in_sizes, int n_in,
                              void* d_out, int out_size)
{
    const float* logits = (const float*)d_in[0];
    const float* boxes  = (const float*)d_in[1];
    float* out = (float*)d_out;

    filter_kernel<<<GRID1, NT1>>>(logits);
    rank_kernel<<<BATCH, NT2>>>(logits, boxes, out);
}

// round 17
// speedup vs baseline: 1.0020x; 1.0020x over previous
#include <cuda_runtime.h>
#include <cstdint>

// DETR-style postprocess, two-phase balanced design:
//   K1: 296 blocks x 1024 thr, element-partitioned stream (perfect SM balance),
//       smem candidate buffer, single coalesced flush per block.
//   K2: 256 blocks x 512 thr, per-batch gather + BITONIC-1024 sort (rank = position).
// Output concatenated flat f32: labels | boxes | scores. (verified R3)

#define BATCH    256
#define QQ       1000
#define CC       80
#define NELEM    80000
#define NV4      20000
#define NV4TOT   (BATCH * NV4)         // 5,120,000 float4
#define KTOP     300
#define CAP      4096
#define NBINS    2048
#define T_STATIC 2.5f

#define GRID1    296
#define NT1      1024
#define QCH      (NV4TOT / GRID1)      // 17297
#define RCH      (NV4TOT % GRID1)      // 88
#define SPLIT    (RCH * (QCH + 1))     // 1,522,224
#define LOCCAP   1024                  // per-chunk cap (mean ~433, sd ~21)

#define NT2      512
#define SORTN    1024                  // bitonic width (M ~ 500 +- 23)

#define LBL_OFF  0
#define BOX_OFF  (BATCH * KTOP)            // 76800
#define SCR_OFF  (BATCH * KTOP * 5)        // 384000

// Per-chunk candidate buffers. g_num is overwritten fresh by every K1 launch.
__device__ unsigned long long g_buf[GRID1][LOCCAP];
__device__ int g_num[GRID1];

__device__ __forceinline__ unsigned f2key(float x) {
    unsigned b = __float_as_uint(x);
    return (b & 0x80000000u) ? ~b : (b | 0x80000000u);
}
__device__ __forceinline__ float key2f(unsigned k) {
    unsigned b = (k & 0x80000000u) ? (k & 0x7FFFFFFFu) : ~k;
    return __uint_as_float(b);
}
__device__ __forceinline__ int chunk_start(int c) {
    return c * QCH + min(c, RCH);
}
__device__ __forceinline__ int blk_of(int x) {   // chunk owning f4 index x
    return (x < SPLIT) ? (x / (QCH + 1)) : (RCH + (x - SPLIT) / QCH);
}

// ------------------------------------------------------------------
// Kernel 1: balanced element-partitioned filter (unchanged, proven)
// ------------------------------------------------------------------
__global__ __launch_bounds__(NT1, 2)
void filter_kernel(const float* __restrict__ logits)
{
    __shared__ __align__(16) unsigned long long s_pack[LOCCAP];
    __shared__ int s_cnt;

    const int blk = blockIdx.x;
    const int tid = threadIdx.x;
    const float4* lg4 = (const float4*)logits;

    const int start = chunk_start(blk);
    const int n     = QCH + (blk < RCH ? 1 : 0);

    if (tid == 0) s_cnt = 0;
    __syncthreads();

    #pragma unroll 1
    for (int it = 0; it < 4; it++) {                  // 4 * 4096 = 16384 f4
        int base = start + it * (4 * NT1) + tid;
        float4 v0 = lg4[base];
        float4 v1 = lg4[base + NT1];
        float4 v2 = lg4[base + 2 * NT1];
        float4 v3 = lg4[base + 3 * NT1];
        float vv[16] = {v0.x, v0.y, v0.z, v0.w,  v1.x, v1.y, v1.z, v1.w,
                        v2.x, v2.y, v2.z, v2.w,  v3.x, v3.y, v3.z, v3.w};
        #pragma unroll
        for (int k = 0; k < 16; k++) {
            if (vv[k] > T_STATIC) {
                int pos = atomicAdd(&s_cnt, 1);
                if (pos < LOCCAP) {
                    unsigned gi = (unsigned)(base + (k >> 2) * NT1) * 4u + (unsigned)(k & 3);
                    s_pack[pos] = ((unsigned long long)f2key(vv[k]) << 32)
                                  | (unsigned long long)(~gi);
                }
            }
        }
    }
    {   // tail: rem in {913, 914} < NT1 -> one guarded load
        int rem = n - 16384;
        if (tid < rem) {
            int x = start + 16384 + tid;
            float4 v = lg4[x];
            float vv[4] = {v.x, v.y, v.z, v.w};
            #pragma unroll
            for (int j = 0; j < 4; j++) {
                if (vv[j] > T_STATIC) {
                    int pos = atomicAdd(&s_cnt, 1);
                    if (pos < LOCCAP) {
                        unsigned gi = (unsigned)x * 4u + (unsigned)j;
                        s_pack[pos] = ((unsigned long long)f2key(vv[j]) << 32)
                                      | (unsigned long long)(~gi);
                    }
                }
            }
        }
    }
    __syncthreads();

    const int cnt  = s_cnt;
    const int my_n = min(cnt, LOCCAP);
    if (tid == 0) g_num[blk] = cnt;
    for (int i = tid; i < my_n; i += NT1)
        g_buf[blk][i] = s_pack[i];
}

// ------------------------------------------------------------------
// Kernel 2: gather + bitonic-1024 rank (O(M^2) retained for fallback)
// ------------------------------------------------------------------
__global__ __launch_bounds__(NT2)
void rank_kernel(const float* __restrict__ logits,
                 const float* __restrict__ boxes,
                 float* __restrict__ out)
{
    __shared__ __align__(16) unsigned long long s_pack[CAP];
    __shared__ unsigned s_hist[NBINS];
    __shared__ int s_cnt, s_ovf;
    __shared__ int s_b1, s_gt, s_b2;

    const int b   = blockIdx.x;
    const int tid = threadIdx.x;
    const float4* lg4 = (const float4*)(logits + (size_t)b * NELEM);

    const unsigned lo = (unsigned)b * (unsigned)NELEM;
    const unsigned hi = lo + (unsigned)NELEM;
    const int c0 = blk_of(b * NV4);
    const int c1 = blk_of(b * NV4 + NV4 - 1);

    if (tid == 0) { s_cnt = 0; s_ovf = 0; }
    __syncthreads();

    // gather candidates belonging to this batch; re-base idx to local
    for (int c = c0; c <= c1; c++) {
        int nc = g_num[c];
        if (nc > LOCCAP) { if (tid == 0) s_ovf = 1; nc = LOCCAP; }
        for (int i = tid; i < nc; i += NT2) {
            unsigned long long p = g_buf[c][i];
            unsigned gi = ~(unsigned)(p & 0xFFFFFFFFull);
            if (gi >= lo && gi < hi) {
                int pos = atomicAdd(&s_cnt, 1);
                if (pos < CAP)
                    s_pack[pos] = (p & 0xFFFFFFFF00000000ull)
                                  | (unsigned long long)(~(gi - lo));
            }
        }
    }
    __syncthreads();
    int M = s_cnt;

    // ---------- Fallback: exact 2-level radix select (statistically never) ----------
    if (M < KTOP || M > CAP || s_ovf) {
        for (int i = tid; i < NBINS; i += NT2) s_hist[i] = 0;
        __syncthreads();
        for (int i = tid; i < NV4; i += NT2) {
            float4 v = lg4[i];
            float vv[4] = {v.x, v.y, v.z, v.w};
            #pragma unroll
            for (int j = 0; j < 4; j++)
                atomicAdd(&s_hist[f2key(vv[j]) >> 21], 1u);
        }
        __syncthreads();
        if (tid == 0) {
            int acc = 0, b1 = 0;
            for (int bin = NBINS - 1; bin >= 0; bin--) {
                int c = (int)s_hist[bin];
                if (acc + c >= KTOP) { b1 = bin; break; }
                acc += c;
            }
            s_b1 = b1; s_gt = acc;
        }
        __syncthreads();
        const int b1 = s_b1;
        const int cnt_ge = s_gt + (int)s_hist[b1];

        if (cnt_ge <= CAP) {
            if (tid == 0) s_cnt = 0;
            __syncthreads();
            for (int i = tid; i < NV4; i += NT2) {
                float4 v = lg4[i];
                float vv[4] = {v.x, v.y, v.z, v.w};
                #pragma unroll
                for (int j = 0; j < 4; j++) {
                    unsigned key = f2key(vv[j]);
                    if ((int)(key >> 21) >= b1) {
                        int pos = atomicAdd(&s_cnt, 1);
                        unsigned idx = (unsigned)(i * 4 + j);
                        s_pack[pos] = ((unsigned long long)key << 32)
                                      | (unsigned long long)(~idx);
                    }
                }
            }
            __syncthreads();
            M = s_cnt;
        } else {
            for (int i = tid; i < NBINS; i += NT2) s_hist[i] = 0;
            __syncthreads();
            for (int i = tid; i < NV4; i += NT2) {
                float4 v = lg4[i];
                float vv[4] = {v.x, v.y, v.z, v.w};
                #pragma unroll
                for (int j = 0; j < 4; j++) {
                    unsigned key = f2key(vv[j]);
                    if ((int)(key >> 21) == b1)
                        atomicAdd(&s_hist[(key >> 10) & 0x7FFu], 1u);
                }
            }
            __syncthreads();
            if (tid == 0) {
                int need = KTOP - s_gt;
                int acc = 0, b2 = 0;
                for (int bin = NBINS - 1; bin >= 0; bin--) {
                    int c = (int)s_hist[bin];
                    if (acc + c >= need) { b2 = bin; break; }
                    acc += c;
                }
                s_b2 = b2; s_cnt = 0;
            }
            __syncthreads();
            const int b2 = s_b2;
            for (int i = tid; i < NV4; i += NT2) {
                float4 v = lg4[i];
                float vv[4] = {v.x, v.y, v.z, v.w};
                #pragma unroll
                for (int j = 0; j < 4; j++) {
                    unsigned key = f2key(vv[j]);
                    int hb = (int)(key >> 21);
                    bool take = (hb > b1) ||
                                (hb == b1 && (int)((key >> 10) & 0x7FFu) >= b2);
                    if (take) {
                        int pos = atomicAdd(&s_cnt, 1);
                        if (pos < CAP) {
                            unsigned idx = (unsigned)(i * 4 + j);
                            s_pack[pos] = ((unsigned long long)key << 32)
                                          | (unsigned long long)(~idx);
                        }
                    }
                }
            }
            __syncthreads();
            M = min(s_cnt, CAP);
        }
    }

    if (M >= KTOP && M <= SORTN) {
        // ---------- Primary rank: bitonic sort (descending), rank = position ----
        for (int i = M + tid; i < SORTN; i += NT2) s_pack[i] = 0ULL;  // pad: sorts last
        __syncthreads();

        #pragma unroll 1
        for (int k = 2; k <= SORTN; k <<= 1) {
            #pragma unroll 1
            for (int j = k >> 1; j > 0; j >>= 1) {
                #pragma unroll
                for (int h = 0; h < SORTN / NT2; h++) {
                    int i = h * NT2 + tid;
                    int ixj = i ^ j;
                    if (ixj > i) {
                        unsigned long long a = s_pack[i], c = s_pack[ixj];
                        bool up = (i & k) != 0;           // up block ascending
                        bool sw = up ? (a > c) : (a < c); // overall descending
                        if (sw) { s_pack[i] = c; s_pack[ixj] = a; }
                    }
                }
                __syncthreads();
            }
        }

        // output: entry r of the sorted list is rank r
        if (tid < KTOP) {
            unsigned long long p = s_pack[tid];
            unsigned key = (unsigned)(p >> 32);
            unsigned idx = ~(unsigned)(p & 0xFFFFFFFFull);
            int q = (int)(idx / CC);
            int c = (int)(idx % CC);
            float lv = key2f(key);
            float score = 1.0f / (1.0f + expf(-lv));

            size_t slot = (size_t)b * KTOP + tid;
            out[LBL_OFF + slot] = (float)c;
            out[SCR_OFF + slot] = score;

            float4 bx = ((const float4*)boxes)[(size_t)b * QQ + q];
            float4 o;
            o.x = bx.x - 0.5f * bx.z;
            o.y = bx.y - 0.5f * bx.w;
            o.z = bx.x + 0.5f * bx.z;
            o.w = bx.y + 0.5f * bx.w;
            ((float4*)(out + BOX_OFF))[slot] = o;
        }
    } else {
        // ---------- Generic rank (fallback lists, M up to CAP): O(M^2) ----------
        if (tid == 0 && M < CAP) s_pack[M] = 0ULL;
        __syncthreads();
        const int Mpair = (M + 1) >> 1;
        const ulonglong2* sp2 = (const ulonglong2*)s_pack;

        for (int i = tid; i < M; i += NT2) {
            unsigned long long pi = s_pack[i];
            int r = 0;
            for (int j = 0; j < Mpair; j++) {
                ulonglong2 pj = sp2[j];
                r += (pj.x > pi) + (pj.y > pi);
            }
            if (r < KTOP) {
                unsigned key = (unsigned)(pi >> 32);
                unsigned idx = ~(unsigned)(pi & 0xFFFFFFFFull);
                int q = (int)(idx / CC);
                int c = (int)(idx % CC);
                float lv = key2f(key);
                float score = 1.0f / (1.0f + expf(-lv));

                size_t slot = (size_t)b * KTOP + r;
                out[LBL_OFF + slot] = (float)c;
                out[SCR_OFF + slot] = score;

                float4 bx = ((const float4*)boxes)[(size_t)b * QQ + q];
                float4 o;
                o.x = bx.x - 0.5f * bx.z;
                o.y = bx.y - 0.5f * bx.w;
                o.z = bx.x + 0.5f * bx.z;
                o.w = bx.y + 0.5f * bx.w;
                ((float4*)(out + BOX_OFF))[slot] = o;
            }
        }
    }
}

extern "C" void kernel_launch(void* const* d_in, const int* in_sizes, int n_in,
                              void* d_out, int out_size)
{
    const float* logits = (const float*)d_in[0];
    const float* boxes  = (const float*)d_in[1];
    float* out = (float*)d_out;

    filter_kernel<<<GRID1, NT1>>>(logits);
    rank_kernel<<<BATCH, NT2>>>(logits, boxes, out);
}